// round 4
// baseline (speedup 1.0000x reference)
#include <cuda_runtime.h>
#include <cuda_fp16.h>

#define NMAX 100000
#define EMAX 3300000   // E + N self loops
#define FIN 512
#define HD  64
#define NITER 10
#define ALPHAF 0.1f
#define SCANB 1024
#define MAXBLK 128     // ceil(NMAX/SCANB) = 98

// ---------------- scratch (device globals; no allocation allowed) ------------
// fp16 feature buffers, 128 B per row, 16B-aligned via uint4
__device__ uint4 g_hv [NMAX * HD / 8];   // MLP output h (fp16)
__device__ uint4 g_z0v[NMAX * HD / 8];   // ping (fp16)
__device__ uint4 g_z1v[NMAX * HD / 8];   // pong (fp16)
__device__ float g_deg[NMAX];            // degree -> dinv (in place)
__device__ int   g_cnt[NMAX];            // in-degree histogram (by col)
__device__ int   g_rowptr[NMAX + 1];     // CSR row pointer (by destination)
__device__ int   g_cursor[NMAX];         // scatter cursors
__device__ int2  g_edge[EMAX];           // CSR: {src, weight-bits fp32}
__device__ int   g_bsum[MAXBLK];         // block sums for scan

// ---------------- preprocessing kernels --------------------------------------

__global__ void zero_kernel(int N) {
    int i = blockIdx.x * blockDim.x + threadIdx.x;
    int stride = gridDim.x * blockDim.x;
    for (; i < N; i += stride) { g_deg[i] = 0.0f; g_cnt[i] = 0; }
}

__global__ void degcnt_kernel(const int* __restrict__ ei,
                              const float* __restrict__ ew, int E, int N) {
    int total = E + N;
    int i = blockIdx.x * blockDim.x + threadIdx.x;
    int stride = gridDim.x * blockDim.x;
    for (; i < total; i += stride) {
        int r, c; float w;
        if (i < E) { r = ei[i]; c = ei[E + i]; w = ew[i]; }
        else       { r = c = i - E; w = 1.0f; }
        atomicAdd(&g_deg[r], w);
        atomicAdd(&g_cnt[c], 1);
    }
}

__global__ void dinv_kernel(int N) {
    int i = blockIdx.x * blockDim.x + threadIdx.x;
    int stride = gridDim.x * blockDim.x;
    for (; i < N; i += stride) {
        float d = g_deg[i];
        g_deg[i] = (d > 0.0f) ? rsqrtf(d) : 0.0f;
    }
}

// ---- 3-phase parallel exclusive scan of g_cnt -> g_rowptr --------------------
__global__ void scan1_kernel(int N) {
    __shared__ int sdata[SCANB];
    int tid = threadIdx.x;
    int i = blockIdx.x * SCANB + tid;
    int v = (i < N) ? g_cnt[i] : 0;
    sdata[tid] = v;
    __syncthreads();
    #pragma unroll
    for (int off = 1; off < SCANB; off <<= 1) {
        int t = (tid >= off) ? sdata[tid - off] : 0;
        __syncthreads();
        sdata[tid] += t;
        __syncthreads();
    }
    if (i < N) g_rowptr[i] = sdata[tid] - v;
    if (tid == SCANB - 1) g_bsum[blockIdx.x] = sdata[tid];
}

__global__ void scan2_kernel(int nblk) {
    __shared__ int sdata[MAXBLK];
    int tid = threadIdx.x;
    int v = (tid < nblk) ? g_bsum[tid] : 0;
    sdata[tid] = v;
    __syncthreads();
    #pragma unroll
    for (int off = 1; off < MAXBLK; off <<= 1) {
        int t = (tid >= off) ? sdata[tid - off] : 0;
        __syncthreads();
        sdata[tid] += t;
        __syncthreads();
    }
    if (tid < nblk) g_bsum[tid] = sdata[tid] - v;
}

__global__ void scan3_kernel(int N, int total) {
    int tid = threadIdx.x;
    int i = blockIdx.x * SCANB + tid;
    if (i < N) {
        int r = g_rowptr[i] + g_bsum[blockIdx.x];
        g_rowptr[i] = r;
        g_cursor[i] = r;
    }
    if (i == N - 1) g_rowptr[N] = total;
}

__global__ void scatter_kernel(const int* __restrict__ ei,
                               const float* __restrict__ ew, int E, int N) {
    int total = E + N;
    int i = blockIdx.x * blockDim.x + threadIdx.x;
    int stride = gridDim.x * blockDim.x;
    for (; i < total; i += stride) {
        int r, c; float w;
        if (i < E) { r = ei[i]; c = ei[E + i]; w = ew[i]; }
        else       { r = c = i - E; w = 1.0f; }
        float wn = g_deg[r] * w * g_deg[c];   // g_deg holds dinv now
        int pos = atomicAdd(&g_cursor[c], 1);
        g_edge[pos] = make_int2(r, __float_as_int(wn));
    }
}

// ---------------- MLP: h = relu(x@W0+b0)@W1+b1 (fp16 out), seeds z0 ----------
// 128 threads, tile 64 rows x 64 cols, 8x4 micro-tile per thread.
__global__ __launch_bounds__(128) void mlp_kernel(
    const float* __restrict__ x,  const float* __restrict__ W0,
    const float* __restrict__ b0, const float* __restrict__ W1,
    const float* __restrict__ b1, int N)
{
    __shared__ float As[64][17];
    __shared__ float Bs[16][64];
    __shared__ float Ts[64][65];
    __shared__ float W1s[64][64];
    __shared__ float b0s[64];
    __shared__ float b1s[64];

    int tid = threadIdx.x;
    int tx = tid & 15;        // col group: cols 4tx..4tx+3
    int ty = tid >> 4;        // row group: rows 8ty..8ty+7
    int row0 = blockIdx.x * 64;

    for (int i = tid; i < 64 * 64; i += 128) W1s[i >> 6][i & 63] = W1[i];
    if (tid < 64) { b0s[tid] = b0[tid]; b1s[tid] = b1[tid]; }

    float acc[8][4] = {};
    // A loader: thread -> row lr (0..63), two float4 slots (8 floats of 16-k chunk)
    int lr = tid >> 1;
    int lq = tid & 1;         // half: floats 8lq..8lq+7
    bool rowok = (row0 + lr) < N;
    const float4* xrow = (const float4*)(x + (size_t)(row0 + lr) * FIN);
    // B loader: row wr (0..15), two float4 slots
    int wr = tid >> 3;
    int wq = tid & 7;

    for (int k0 = 0; k0 < FIN; k0 += 16) {
        #pragma unroll
        for (int q = 0; q < 2; q++) {
            int slot = 2 * lq + q;      // float4 slot 0..3 in 16 floats
            float4 xa = rowok ? xrow[(k0 >> 2) + slot]
                              : make_float4(0.f, 0.f, 0.f, 0.f);
            As[lr][4 * slot + 0] = xa.x; As[lr][4 * slot + 1] = xa.y;
            As[lr][4 * slot + 2] = xa.z; As[lr][4 * slot + 3] = xa.w;
        }
        #pragma unroll
        for (int q = 0; q < 2; q++) {
            int slot = wq + 8 * q;      // float4 slot 0..15 in 64 cols
            float4 wb = *(const float4*)(W0 + (size_t)(k0 + wr) * HD + 4 * slot);
            Bs[wr][4 * slot + 0] = wb.x; Bs[wr][4 * slot + 1] = wb.y;
            Bs[wr][4 * slot + 2] = wb.z; Bs[wr][4 * slot + 3] = wb.w;
        }
        __syncthreads();
        #pragma unroll
        for (int kk = 0; kk < 16; kk++) {
            float a[8];
            #pragma unroll
            for (int i = 0; i < 8; i++) a[i] = As[8 * ty + i][kk];
            float c0 = Bs[kk][4 * tx + 0], c1 = Bs[kk][4 * tx + 1];
            float c2 = Bs[kk][4 * tx + 2], c3 = Bs[kk][4 * tx + 3];
            #pragma unroll
            for (int i = 0; i < 8; i++) {
                acc[i][0] += a[i] * c0; acc[i][1] += a[i] * c1;
                acc[i][2] += a[i] * c2; acc[i][3] += a[i] * c3;
            }
        }
        __syncthreads();
    }

    // bias + relu -> Ts
    #pragma unroll
    for (int i = 0; i < 8; i++)
        #pragma unroll
        for (int j = 0; j < 4; j++) {
            float v = acc[i][j] + b0s[4 * tx + j];
            Ts[8 * ty + i][4 * tx + j] = v > 0.f ? v : 0.f;
        }
    __syncthreads();

    // stage B: h = Ts @ W1 + b1
    float acc2[8][4] = {};
    #pragma unroll 4
    for (int k = 0; k < 64; k++) {
        float a[8];
        #pragma unroll
        for (int i = 0; i < 8; i++) a[i] = Ts[8 * ty + i][k];
        float c0 = W1s[k][4 * tx + 0], c1 = W1s[k][4 * tx + 1];
        float c2 = W1s[k][4 * tx + 2], c3 = W1s[k][4 * tx + 3];
        #pragma unroll
        for (int i = 0; i < 8; i++) {
            acc2[i][0] += a[i] * c0; acc2[i][1] += a[i] * c1;
            acc2[i][2] += a[i] * c2; acc2[i][3] += a[i] * c3;
        }
    }

    __half* gh = (__half*)g_hv;
    __half* gz = (__half*)g_z0v;
    #pragma unroll
    for (int i = 0; i < 8; i++) {
        int row = row0 + 8 * ty + i;
        if (row < N) {
            float v0 = acc2[i][0] + b1s[4 * tx + 0];
            float v1 = acc2[i][1] + b1s[4 * tx + 1];
            float v2 = acc2[i][2] + b1s[4 * tx + 2];
            float v3 = acc2[i][3] + b1s[4 * tx + 3];
            __half2 p0 = __float22half2_rn(make_float2(v0, v1));
            __half2 p1 = __float22half2_rn(make_float2(v2, v3));
            uint2 u;
            u.x = *(unsigned int*)&p0;
            u.y = *(unsigned int*)&p1;
            *(uint2*)(gh + (size_t)row * HD + 4 * tx) = u;
            *(uint2*)(gz + (size_t)row * HD + 4 * tx) = u;
        }
    }
}

// ---------------- propagation: 8 lanes per destination node ------------------
// Each edge gather = one LDG.128 x 8 lanes = exactly one 128B row of fp16 z.
__global__ __launch_bounds__(256) void prop_kernel(int iter, float* __restrict__ dout,
                                                   int N, int niter)
{
    int node = (blockIdx.x * blockDim.x + threadIdx.x) >> 3;
    int lane = threadIdx.x & 7;
    if (node >= N) return;

    const __half* zin = (const __half*)((iter & 1) ? g_z1v : g_z0v);
    __half* zout16 = (__half*)((iter & 1) ? g_z0v : g_z1v);

    int start = g_rowptr[node];
    int end   = g_rowptr[node + 1];

    float acc[8] = {};
    for (int e0 = start; e0 < end; e0 += 8) {
        int e = e0 + lane;
        int2 ed = make_int2(0, 0);
        if (e < end) ed = g_edge[e];
        int m = min(8, end - e0);
        #pragma unroll 8
        for (int j = 0; j < m; j++) {
            int   sj = __shfl_sync(0xffffffffu, ed.x, j, 8);
            float wj = __int_as_float(__shfl_sync(0xffffffffu, ed.y, j, 8));
            uint4 v = *(const uint4*)(zin + (size_t)sj * HD + 8 * lane);
            float2 f0 = __half22float2(*(__half2*)&v.x);
            float2 f1 = __half22float2(*(__half2*)&v.y);
            float2 f2 = __half22float2(*(__half2*)&v.z);
            float2 f3 = __half22float2(*(__half2*)&v.w);
            acc[0] += wj * f0.x; acc[1] += wj * f0.y;
            acc[2] += wj * f1.x; acc[3] += wj * f1.y;
            acc[4] += wj * f2.x; acc[5] += wj * f2.y;
            acc[6] += wj * f3.x; acc[7] += wj * f3.y;
        }
    }

    // blend with teleport term
    const __half* gh = (const __half*)g_hv;
    uint4 hv = *(const uint4*)(gh + (size_t)node * HD + 8 * lane);
    float2 h0 = __half22float2(*(__half2*)&hv.x);
    float2 h1 = __half22float2(*(__half2*)&hv.y);
    float2 h2 = __half22float2(*(__half2*)&hv.z);
    float2 h3 = __half22float2(*(__half2*)&hv.w);
    float o[8];
    o[0] = (1.0f - ALPHAF) * acc[0] + ALPHAF * h0.x;
    o[1] = (1.0f - ALPHAF) * acc[1] + ALPHAF * h0.y;
    o[2] = (1.0f - ALPHAF) * acc[2] + ALPHAF * h1.x;
    o[3] = (1.0f - ALPHAF) * acc[3] + ALPHAF * h1.y;
    o[4] = (1.0f - ALPHAF) * acc[4] + ALPHAF * h2.x;
    o[5] = (1.0f - ALPHAF) * acc[5] + ALPHAF * h2.y;
    o[6] = (1.0f - ALPHAF) * acc[6] + ALPHAF * h3.x;
    o[7] = (1.0f - ALPHAF) * acc[7] + ALPHAF * h3.y;

    if (iter == niter - 1) {
        // final: write fp32 directly (never rounded to fp16)
        float4 w0 = make_float4(o[0], o[1], o[2], o[3]);
        float4 w1 = make_float4(o[4], o[5], o[6], o[7]);
        float* dst = dout + (size_t)node * HD + 8 * lane;
        *(float4*)(dst + 0) = w0;
        *(float4*)(dst + 4) = w1;
    } else {
        __half2 p0 = __float22half2_rn(make_float2(o[0], o[1]));
        __half2 p1 = __float22half2_rn(make_float2(o[2], o[3]));
        __half2 p2 = __float22half2_rn(make_float2(o[4], o[5]));
        __half2 p3 = __float22half2_rn(make_float2(o[6], o[7]));
        uint4 u;
        u.x = *(unsigned int*)&p0;
        u.y = *(unsigned int*)&p1;
        u.z = *(unsigned int*)&p2;
        u.w = *(unsigned int*)&p3;
        *(uint4*)(zout16 + (size_t)node * HD + 8 * lane) = u;
    }
}

// ---------------- launcher ----------------------------------------------------
extern "C" void kernel_launch(void* const* d_in, const int* in_sizes, int n_in,
                              void* d_out, int out_size)
{
    const float* x  = (const float*)d_in[0];
    const int*   ei = (const int*)  d_in[1];
    const float* ew = (const float*)d_in[2];
    const float* W0 = (const float*)d_in[3];
    const float* b0 = (const float*)d_in[4];
    const float* W1 = (const float*)d_in[5];
    const float* b1 = (const float*)d_in[6];
    float* out = (float*)d_out;

    int N = in_sizes[0] / FIN;
    int E = in_sizes[2];
    int total = E + N;

    int tpb = 256;
    int nblk = (N + tpb - 1) / tpb;
    int eblk = (total + tpb - 1) / tpb;
    if (eblk > 4096) eblk = 4096;
    int sblk = (N + SCANB - 1) / SCANB;

    zero_kernel<<<nblk, tpb>>>(N);
    degcnt_kernel<<<eblk, tpb>>>(ei, ew, E, N);
    dinv_kernel<<<nblk, tpb>>>(N);
    scan1_kernel<<<sblk, SCANB>>>(N);
    scan2_kernel<<<1, MAXBLK>>>(sblk);
    scan3_kernel<<<sblk, SCANB>>>(N, total);
    scatter_kernel<<<eblk, tpb>>>(ei, ew, E, N);
    mlp_kernel<<<(N + 63) / 64, 128>>>(x, W0, b0, W1, b1, N);

    int pblk = (N * 8 + tpb - 1) / tpb;
    for (int it = 0; it < NITER; it++)
        prop_kernel<<<pblk, tpb>>>(it, out, N, NITER);
}

// round 5
// speedup vs baseline: 1.2665x; 1.2665x over previous
#include <cuda_runtime.h>
#include <cuda_fp16.h>

#define NMAX 100000
#define EMAX 3300000   // E + N self loops
#define FIN 512
#define HD  64
#define NITER 10
#define ALPHAF 0.1f
#define SCANB 1024
#define MAXBLK 128     // ceil(NMAX/SCANB) = 98

// ---------------- scratch (device globals; no allocation allowed) ------------
__device__ uint4 g_hv [NMAX * HD / 8];   // MLP output h (fp16)
__device__ uint4 g_z0v[NMAX * HD / 8];   // ping (fp16)
__device__ uint4 g_z1v[NMAX * HD / 8];   // pong (fp16)
__device__ float g_deg[NMAX];            // degree -> dinv (in place)
__device__ int   g_cnt[NMAX];            // in-degree histogram (by col)
__device__ int   g_rowptr[NMAX + 1];     // CSR row pointer (by destination)
__device__ int   g_cursor[NMAX];         // scatter cursors
__device__ int2  g_edge[EMAX];           // CSR: {src, weight-bits fp32}
__device__ int   g_bsum[MAXBLK];         // block sums for scan

// ---------------- preprocessing kernels --------------------------------------

__global__ void zero_kernel(int N) {
    int i = blockIdx.x * blockDim.x + threadIdx.x;
    int stride = gridDim.x * blockDim.x;
    for (; i < N; i += stride) { g_deg[i] = 0.0f; g_cnt[i] = 0; }
}

__global__ void degcnt_kernel(const int* __restrict__ ei,
                              const float* __restrict__ ew, int E, int N) {
    int total = E + N;
    int i = blockIdx.x * blockDim.x + threadIdx.x;
    int stride = gridDim.x * blockDim.x;
    for (; i < total; i += stride) {
        int r, c; float w;
        if (i < E) { r = ei[i]; c = ei[E + i]; w = ew[i]; }
        else       { r = c = i - E; w = 1.0f; }
        atomicAdd(&g_deg[r], w);
        atomicAdd(&g_cnt[c], 1);
    }
}

__global__ void dinv_kernel(int N) {
    int i = blockIdx.x * blockDim.x + threadIdx.x;
    int stride = gridDim.x * blockDim.x;
    for (; i < N; i += stride) {
        float d = g_deg[i];
        g_deg[i] = (d > 0.0f) ? rsqrtf(d) : 0.0f;
    }
}

// ---- 3-phase parallel exclusive scan of g_cnt -> g_rowptr --------------------
__global__ void scan1_kernel(int N) {
    __shared__ int sdata[SCANB];
    int tid = threadIdx.x;
    int i = blockIdx.x * SCANB + tid;
    int v = (i < N) ? g_cnt[i] : 0;
    sdata[tid] = v;
    __syncthreads();
    #pragma unroll
    for (int off = 1; off < SCANB; off <<= 1) {
        int t = (tid >= off) ? sdata[tid - off] : 0;
        __syncthreads();
        sdata[tid] += t;
        __syncthreads();
    }
    if (i < N) g_rowptr[i] = sdata[tid] - v;
    if (tid == SCANB - 1) g_bsum[blockIdx.x] = sdata[tid];
}

__global__ void scan2_kernel(int nblk) {
    __shared__ int sdata[MAXBLK];
    int tid = threadIdx.x;
    int v = (tid < nblk) ? g_bsum[tid] : 0;
    sdata[tid] = v;
    __syncthreads();
    #pragma unroll
    for (int off = 1; off < MAXBLK; off <<= 1) {
        int t = (tid >= off) ? sdata[tid - off] : 0;
        __syncthreads();
        sdata[tid] += t;
        __syncthreads();
    }
    if (tid < nblk) g_bsum[tid] = sdata[tid] - v;
}

__global__ void scan3_kernel(int N, int total) {
    int tid = threadIdx.x;
    int i = blockIdx.x * SCANB + tid;
    if (i < N) {
        int r = g_rowptr[i] + g_bsum[blockIdx.x];
        g_rowptr[i] = r;
        g_cursor[i] = r;
    }
    if (i == N - 1) g_rowptr[N] = total;
}

__global__ void scatter_kernel(const int* __restrict__ ei,
                               const float* __restrict__ ew, int E, int N) {
    int total = E + N;
    int i = blockIdx.x * blockDim.x + threadIdx.x;
    int stride = gridDim.x * blockDim.x;
    for (; i < total; i += stride) {
        int r, c; float w;
        if (i < E) { r = ei[i]; c = ei[E + i]; w = ew[i]; }
        else       { r = c = i - E; w = 1.0f; }
        float wn = g_deg[r] * w * g_deg[c];   // g_deg holds dinv now
        int pos = atomicAdd(&g_cursor[c], 1);
        g_edge[pos] = make_int2(r, __float_as_int(wn));
    }
}

// ---------------- MLP: h = relu(x@W0+b0)@W1+b1 (fp16 out), seeds z0 ----------
// block = 256 threads, tile = 64 rows x 64 cols, 4x4 micro-tile per thread.
// (proven R2 structure; only the stores changed to fp16)
__global__ __launch_bounds__(256) void mlp_kernel(
    const float* __restrict__ x,  const float* __restrict__ W0,
    const float* __restrict__ b0, const float* __restrict__ W1,
    const float* __restrict__ b1, int N)
{
    __shared__ float As[64][17];
    __shared__ float Bs[16][64];
    __shared__ float Ts[64][65];
    __shared__ float W1s[64][64];
    __shared__ float b0s[64];
    __shared__ float b1s[64];

    int tid = threadIdx.x;
    int tx = tid & 15, ty = tid >> 4;
    int row0 = blockIdx.x * 64;

    for (int i = tid; i < 64 * 64; i += 256) W1s[i >> 6][i & 63] = W1[i];
    if (tid < 64) { b0s[tid] = b0[tid]; b1s[tid] = b1[tid]; }

    float acc[4][4] = {};
    int lr = tid >> 2;
    int lq = tid & 3;
    bool rowok = (row0 + lr) < N;
    const float4* xrow = (const float4*)(x + (size_t)(row0 + lr) * FIN);
    int wr = tid >> 4;
    int wq = tid & 15;

    for (int k0 = 0; k0 < FIN; k0 += 16) {
        float4 xa = rowok ? xrow[(k0 >> 2) + lq] : make_float4(0.f, 0.f, 0.f, 0.f);
        As[lr][4 * lq + 0] = xa.x; As[lr][4 * lq + 1] = xa.y;
        As[lr][4 * lq + 2] = xa.z; As[lr][4 * lq + 3] = xa.w;
        float4 wb = *(const float4*)(W0 + (size_t)(k0 + wr) * HD + 4 * wq);
        Bs[wr][4 * wq + 0] = wb.x; Bs[wr][4 * wq + 1] = wb.y;
        Bs[wr][4 * wq + 2] = wb.z; Bs[wr][4 * wq + 3] = wb.w;
        __syncthreads();
        #pragma unroll
        for (int kk = 0; kk < 16; kk++) {
            float a0 = As[4 * ty + 0][kk], a1 = As[4 * ty + 1][kk];
            float a2 = As[4 * ty + 2][kk], a3 = As[4 * ty + 3][kk];
            float c0 = Bs[kk][4 * tx + 0], c1 = Bs[kk][4 * tx + 1];
            float c2 = Bs[kk][4 * tx + 2], c3 = Bs[kk][4 * tx + 3];
            acc[0][0] += a0 * c0; acc[0][1] += a0 * c1; acc[0][2] += a0 * c2; acc[0][3] += a0 * c3;
            acc[1][0] += a1 * c0; acc[1][1] += a1 * c1; acc[1][2] += a1 * c2; acc[1][3] += a1 * c3;
            acc[2][0] += a2 * c0; acc[2][1] += a2 * c1; acc[2][2] += a2 * c2; acc[2][3] += a2 * c3;
            acc[3][0] += a3 * c0; acc[3][1] += a3 * c1; acc[3][2] += a3 * c2; acc[3][3] += a3 * c3;
        }
        __syncthreads();
    }

    #pragma unroll
    for (int i = 0; i < 4; i++)
        #pragma unroll
        for (int j = 0; j < 4; j++) {
            float v = acc[i][j] + b0s[4 * tx + j];
            Ts[4 * ty + i][4 * tx + j] = v > 0.f ? v : 0.f;
        }
    __syncthreads();

    float acc2[4][4] = {};
    #pragma unroll 8
    for (int k = 0; k < 64; k++) {
        float a0 = Ts[4 * ty + 0][k], a1 = Ts[4 * ty + 1][k];
        float a2 = Ts[4 * ty + 2][k], a3 = Ts[4 * ty + 3][k];
        float c0 = W1s[k][4 * tx + 0], c1 = W1s[k][4 * tx + 1];
        float c2 = W1s[k][4 * tx + 2], c3 = W1s[k][4 * tx + 3];
        acc2[0][0] += a0 * c0; acc2[0][1] += a0 * c1; acc2[0][2] += a0 * c2; acc2[0][3] += a0 * c3;
        acc2[1][0] += a1 * c0; acc2[1][1] += a1 * c1; acc2[1][2] += a1 * c2; acc2[1][3] += a1 * c3;
        acc2[2][0] += a2 * c0; acc2[2][1] += a2 * c1; acc2[2][2] += a2 * c2; acc2[2][3] += a2 * c3;
        acc2[3][0] += a3 * c0; acc2[3][1] += a3 * c1; acc2[3][2] += a3 * c2; acc2[3][3] += a3 * c3;
    }

    __half* gh = (__half*)g_hv;
    __half* gz = (__half*)g_z0v;
    #pragma unroll
    for (int i = 0; i < 4; i++) {
        int row = row0 + 4 * ty + i;
        if (row < N) {
            float v0 = acc2[i][0] + b1s[4 * tx + 0];
            float v1 = acc2[i][1] + b1s[4 * tx + 1];
            float v2 = acc2[i][2] + b1s[4 * tx + 2];
            float v3 = acc2[i][3] + b1s[4 * tx + 3];
            __half2 p0 = __float22half2_rn(make_float2(v0, v1));
            __half2 p1 = __float22half2_rn(make_float2(v2, v3));
            uint2 u;
            u.x = *(unsigned int*)&p0;
            u.y = *(unsigned int*)&p1;
            *(uint2*)(gh + (size_t)row * HD + 4 * tx) = u;
            *(uint2*)(gz + (size_t)row * HD + 4 * tx) = u;
        }
    }
}

// ---------------- propagation: 16 lanes per destination node -----------------
// fp16 z: 16 lanes x uint2 (8B) = exactly one 128B line per gathered row.
__global__ __launch_bounds__(256) void prop_kernel(int iter, float* __restrict__ dout,
                                                   int N, int niter)
{
    int node = (blockIdx.x * blockDim.x + threadIdx.x) >> 4;
    int lane = threadIdx.x & 15;
    if (node >= N) return;

    const __half* zin = (const __half*)((iter & 1) ? g_z1v : g_z0v);
    __half* zout16 = (__half*)((iter & 1) ? g_z0v : g_z1v);

    int start = g_rowptr[node];
    int end   = g_rowptr[node + 1];

    float acc[4] = {};
    for (int e0 = start; e0 < end; e0 += 16) {
        int e = e0 + lane;
        int2 ed = make_int2(0, 0);
        if (e < end) ed = g_edge[e];
        int m = min(16, end - e0);
        #pragma unroll 4
        for (int j = 0; j < m; j++) {
            int   sj = __shfl_sync(0xffffffffu, ed.x, j, 16);
            float wj = __int_as_float(__shfl_sync(0xffffffffu, ed.y, j, 16));
            uint2 v = *(const uint2*)(zin + (size_t)sj * HD + 4 * lane);
            float2 f0 = __half22float2(*(__half2*)&v.x);
            float2 f1 = __half22float2(*(__half2*)&v.y);
            acc[0] += wj * f0.x; acc[1] += wj * f0.y;
            acc[2] += wj * f1.x; acc[3] += wj * f1.y;
        }
    }

    // blend with teleport term
    const __half* gh = (const __half*)g_hv;
    uint2 hv = *(const uint2*)(gh + (size_t)node * HD + 4 * lane);
    float2 h0 = __half22float2(*(__half2*)&hv.x);
    float2 h1 = __half22float2(*(__half2*)&hv.y);
    float o0 = (1.0f - ALPHAF) * acc[0] + ALPHAF * h0.x;
    float o1 = (1.0f - ALPHAF) * acc[1] + ALPHAF * h0.y;
    float o2 = (1.0f - ALPHAF) * acc[2] + ALPHAF * h1.x;
    float o3 = (1.0f - ALPHAF) * acc[3] + ALPHAF * h1.y;

    if (iter == niter - 1) {
        // final: write fp32 directly (never rounded to fp16)
        *(float4*)(dout + (size_t)node * HD + 4 * lane) = make_float4(o0, o1, o2, o3);
    } else {
        __half2 p0 = __float22half2_rn(make_float2(o0, o1));
        __half2 p1 = __float22half2_rn(make_float2(o2, o3));
        uint2 u;
        u.x = *(unsigned int*)&p0;
        u.y = *(unsigned int*)&p1;
        *(uint2*)(zout16 + (size_t)node * HD + 4 * lane) = u;
    }
}

// ---------------- launcher ----------------------------------------------------
extern "C" void kernel_launch(void* const* d_in, const int* in_sizes, int n_in,
                              void* d_out, int out_size)
{
    const float* x  = (const float*)d_in[0];
    const int*   ei = (const int*)  d_in[1];
    const float* ew = (const float*)d_in[2];
    const float* W0 = (const float*)d_in[3];
    const float* b0 = (const float*)d_in[4];
    const float* W1 = (const float*)d_in[5];
    const float* b1 = (const float*)d_in[6];
    float* out = (float*)d_out;

    int N = in_sizes[0] / FIN;
    int E = in_sizes[2];
    int total = E + N;

    int tpb = 256;
    int nblk = (N + tpb - 1) / tpb;
    int eblk = (total + tpb - 1) / tpb;
    if (eblk > 4096) eblk = 4096;
    int sblk = (N + SCANB - 1) / SCANB;

    zero_kernel<<<nblk, tpb>>>(N);
    degcnt_kernel<<<eblk, tpb>>>(ei, ew, E, N);
    dinv_kernel<<<nblk, tpb>>>(N);
    scan1_kernel<<<sblk, SCANB>>>(N);
    scan2_kernel<<<1, MAXBLK>>>(sblk);
    scan3_kernel<<<sblk, SCANB>>>(N, total);
    scatter_kernel<<<eblk, tpb>>>(ei, ew, E, N);
    mlp_kernel<<<(N + 63) / 64, 256>>>(x, W0, b0, W1, b1, N);

    int pblk = (N * 16 + tpb - 1) / tpb;
    for (int it = 0; it < NITER; it++)
        prop_kernel<<<pblk, tpb>>>(it, out, N, NITER);
}

// round 6
// speedup vs baseline: 1.4532x; 1.1474x over previous
#include <cuda_runtime.h>
#include <cuda_fp16.h>

#define NMAX 100000
#define EMAX 3300000   // E + N self loops
#define FIN 512
#define HD  64
#define NITER 10
#define ALPHAF 0.1f
#define SCANB 1024
#define MAXBLK 128     // ceil(NMAX/SCANB) = 98

// ---------------- scratch (device globals; no allocation allowed) ------------
__device__ uint4 g_hv [NMAX * HD / 8];   // MLP output h (fp16)
__device__ uint4 g_z0v[NMAX * HD / 8];   // ping (fp16)
__device__ uint4 g_z1v[NMAX * HD / 8];   // pong (fp16)
__device__ float g_deg[NMAX];            // degree -> dinv (in place)
__device__ int   g_cnt[NMAX];            // in-degree histogram (by col)
__device__ int   g_rowptr[NMAX + 1];     // CSR row pointer (by destination)
__device__ int   g_cursor[NMAX];         // scatter cursors
__device__ int2  g_edge[EMAX];           // CSR: {src, weight-bits fp32}
__device__ int   g_bsum[MAXBLK];         // block sums for scan

// ---------------- preprocessing kernels --------------------------------------

__global__ void zero_kernel(int N) {
    int i = blockIdx.x * blockDim.x + threadIdx.x;
    int stride = gridDim.x * blockDim.x;
    for (; i < N; i += stride) { g_deg[i] = 0.0f; g_cnt[i] = 0; }
}

__global__ void degcnt_kernel(const int* __restrict__ ei,
                              const float* __restrict__ ew, int E, int N) {
    int total = E + N;
    int i = blockIdx.x * blockDim.x + threadIdx.x;
    int stride = gridDim.x * blockDim.x;
    for (; i < total; i += stride) {
        int r, c; float w;
        if (i < E) { r = ei[i]; c = ei[E + i]; w = ew[i]; }
        else       { r = c = i - E; w = 1.0f; }
        atomicAdd(&g_deg[r], w);
        atomicAdd(&g_cnt[c], 1);
    }
}

__global__ void dinv_kernel(int N) {
    int i = blockIdx.x * blockDim.x + threadIdx.x;
    int stride = gridDim.x * blockDim.x;
    for (; i < N; i += stride) {
        float d = g_deg[i];
        g_deg[i] = (d > 0.0f) ? rsqrtf(d) : 0.0f;
    }
}

// ---- 3-phase parallel exclusive scan of g_cnt -> g_rowptr --------------------
__global__ void scan1_kernel(int N) {
    __shared__ int sdata[SCANB];
    int tid = threadIdx.x;
    int i = blockIdx.x * SCANB + tid;
    int v = (i < N) ? g_cnt[i] : 0;
    sdata[tid] = v;
    __syncthreads();
    #pragma unroll
    for (int off = 1; off < SCANB; off <<= 1) {
        int t = (tid >= off) ? sdata[tid - off] : 0;
        __syncthreads();
        sdata[tid] += t;
        __syncthreads();
    }
    if (i < N) g_rowptr[i] = sdata[tid] - v;
    if (tid == SCANB - 1) g_bsum[blockIdx.x] = sdata[tid];
}

__global__ void scan2_kernel(int nblk) {
    __shared__ int sdata[MAXBLK];
    int tid = threadIdx.x;
    int v = (tid < nblk) ? g_bsum[tid] : 0;
    sdata[tid] = v;
    __syncthreads();
    #pragma unroll
    for (int off = 1; off < MAXBLK; off <<= 1) {
        int t = (tid >= off) ? sdata[tid - off] : 0;
        __syncthreads();
        sdata[tid] += t;
        __syncthreads();
    }
    if (tid < nblk) g_bsum[tid] = sdata[tid] - v;
}

__global__ void scan3_kernel(int N, int total) {
    int tid = threadIdx.x;
    int i = blockIdx.x * SCANB + tid;
    if (i < N) {
        int r = g_rowptr[i] + g_bsum[blockIdx.x];
        g_rowptr[i] = r;
        g_cursor[i] = r;
    }
    if (i == N - 1) g_rowptr[N] = total;
}

__global__ void scatter_kernel(const int* __restrict__ ei,
                               const float* __restrict__ ew, int E, int N) {
    int total = E + N;
    int i = blockIdx.x * blockDim.x + threadIdx.x;
    int stride = gridDim.x * blockDim.x;
    for (; i < total; i += stride) {
        int r, c; float w;
        if (i < E) { r = ei[i]; c = ei[E + i]; w = ew[i]; }
        else       { r = c = i - E; w = 1.0f; }
        float wn = g_deg[r] * w * g_deg[c];   // g_deg holds dinv now
        int pos = atomicAdd(&g_cursor[c], 1);
        g_edge[pos] = make_int2(r, __float_as_int(wn));
    }
}

// ---------------- MLP via tensor cores (mma.sync m16n8k16 f16->f32) ----------
// Block: 256 threads (8 warps), tile 128 rows x 64 cols.
// Each warp: 16-row strip, 8 n-tiles of width 8.
#define AS_STRIDE 36   // 32 k + pad; 72B/row -> 8 consecutive rows hit 8 distinct banks
#define TS_STRIDE 68   // 64 + pad; 136B/row -> distinct banks

__device__ __forceinline__ void mma16816(float c[4],
                                         unsigned a0, unsigned a1, unsigned a2, unsigned a3,
                                         unsigned b0, unsigned b1) {
    asm volatile(
        "mma.sync.aligned.m16n8k16.row.col.f32.f16.f16.f32 "
        "{%0,%1,%2,%3}, {%4,%5,%6,%7}, {%8,%9}, {%0,%1,%2,%3};"
        : "+f"(c[0]), "+f"(c[1]), "+f"(c[2]), "+f"(c[3])
        : "r"(a0), "r"(a1), "r"(a2), "r"(a3), "r"(b0), "r"(b1));
}

__global__ __launch_bounds__(256) void mlp_kernel(
    const float* __restrict__ x,  const float* __restrict__ W0,
    const float* __restrict__ b0, const float* __restrict__ W1,
    const float* __restrict__ b1, int N)
{
    __shared__ __half As[128][AS_STRIDE];   // x chunk, row-major [row][k]
    __shared__ __half Bs[64][AS_STRIDE];    // W0 chunk, n-major [n][k]
    __shared__ __half Ts[128][TS_STRIDE];   // relu(x@W0+b0) fp16, [row][n]
    __shared__ __half W1s[64][TS_STRIDE];   // W1, n-major [n][k]
    __shared__ float b0s[64];
    __shared__ float b1s[64];

    int tid  = threadIdx.x;
    int wid  = tid >> 5;
    int lane = tid & 31;
    int g = lane >> 2;        // 0..7
    int t = lane & 3;         // 0..3
    int wr0 = wid * 16;       // warp's row strip within tile
    int row0 = blockIdx.x * 128;

    // preload W1 (transposed to n-major) and biases
    for (int i = tid; i < 64 * 64; i += 256) {
        int k = i >> 6, n = i & 63;
        W1s[n][k] = __float2half(W1[i]);
    }
    if (tid < 64) { b0s[tid] = b0[tid]; b1s[tid] = b1[tid]; }

    float c1a[8][4] = {};

    // ---- stage 1: T = relu(x @ W0 + b0), K = 512 in chunks of 32 ----
    int lr = tid >> 1;            // x loader row 0..127
    int lq = tid & 1;             // which 16-col half
    bool rowok = (row0 + lr) < N;
    const float* xrow = x + (size_t)(row0 + lr) * FIN;

    for (int k0 = 0; k0 < FIN; k0 += 32) {
        // load x chunk 128x32 f32 -> fp16 smem
        #pragma unroll
        for (int jj = 0; jj < 4; jj++) {
            float4 v = rowok ? *(const float4*)(xrow + k0 + 16 * lq + 4 * jj)
                             : make_float4(0.f, 0.f, 0.f, 0.f);
            *(__half2*)&As[lr][16 * lq + 4 * jj]     = __floats2half2_rn(v.x, v.y);
            *(__half2*)&As[lr][16 * lq + 4 * jj + 2] = __floats2half2_rn(v.z, v.w);
        }
        // load W0 chunk 32x64 f32 -> transposed fp16 smem [n][k]
        for (int i = tid; i < 32 * 64; i += 256) {
            int kr = i >> 6, nc = i & 63;
            Bs[nc][kr] = __float2half(W0[(size_t)(k0 + kr) * HD + nc]);
        }
        __syncthreads();

        #pragma unroll
        for (int kk = 0; kk < 32; kk += 16) {
            unsigned a0 = *(const unsigned*)&As[wr0 + g][kk + 2 * t];
            unsigned a1 = *(const unsigned*)&As[wr0 + g + 8][kk + 2 * t];
            unsigned a2 = *(const unsigned*)&As[wr0 + g][kk + 2 * t + 8];
            unsigned a3 = *(const unsigned*)&As[wr0 + g + 8][kk + 2 * t + 8];
            #pragma unroll
            for (int nt = 0; nt < 8; nt++) {
                unsigned bb0 = *(const unsigned*)&Bs[nt * 8 + g][kk + 2 * t];
                unsigned bb1 = *(const unsigned*)&Bs[nt * 8 + g][kk + 2 * t + 8];
                mma16816(c1a[nt], a0, a1, a2, a3, bb0, bb1);
            }
        }
        __syncthreads();
    }

    // bias + relu -> Ts (fp16)
    #pragma unroll
    for (int nt = 0; nt < 8; nt++) {
        int col = nt * 8 + 2 * t;
        float v0 = fmaxf(c1a[nt][0] + b0s[col], 0.f);
        float v1 = fmaxf(c1a[nt][1] + b0s[col + 1], 0.f);
        float v2 = fmaxf(c1a[nt][2] + b0s[col], 0.f);
        float v3 = fmaxf(c1a[nt][3] + b0s[col + 1], 0.f);
        *(__half2*)&Ts[wr0 + g][col]     = __floats2half2_rn(v0, v1);
        *(__half2*)&Ts[wr0 + g + 8][col] = __floats2half2_rn(v2, v3);
    }
    __syncthreads();

    // ---- stage 2: h = T @ W1 + b1, K = 64 ----
    float c2a[8][4] = {};
    #pragma unroll
    for (int kk = 0; kk < 64; kk += 16) {
        unsigned a0 = *(const unsigned*)&Ts[wr0 + g][kk + 2 * t];
        unsigned a1 = *(const unsigned*)&Ts[wr0 + g + 8][kk + 2 * t];
        unsigned a2 = *(const unsigned*)&Ts[wr0 + g][kk + 2 * t + 8];
        unsigned a3 = *(const unsigned*)&Ts[wr0 + g + 8][kk + 2 * t + 8];
        #pragma unroll
        for (int nt = 0; nt < 8; nt++) {
            unsigned bb0 = *(const unsigned*)&W1s[nt * 8 + g][kk + 2 * t];
            unsigned bb1 = *(const unsigned*)&W1s[nt * 8 + g][kk + 2 * t + 8];
            mma16816(c2a[nt], a0, a1, a2, a3, bb0, bb1);
        }
    }

    // bias + store h, z0 (fp16)
    __half* gh = (__half*)g_hv;
    __half* gz = (__half*)g_z0v;
    int r0 = row0 + wr0 + g;
    int r1 = r0 + 8;
    #pragma unroll
    for (int nt = 0; nt < 8; nt++) {
        int col = nt * 8 + 2 * t;
        __half2 lo = __floats2half2_rn(c2a[nt][0] + b1s[col], c2a[nt][1] + b1s[col + 1]);
        __half2 hi = __floats2half2_rn(c2a[nt][2] + b1s[col], c2a[nt][3] + b1s[col + 1]);
        if (r0 < N) {
            *(__half2*)(gh + (size_t)r0 * HD + col) = lo;
            *(__half2*)(gz + (size_t)r0 * HD + col) = lo;
        }
        if (r1 < N) {
            *(__half2*)(gh + (size_t)r1 * HD + col) = hi;
            *(__half2*)(gz + (size_t)r1 * HD + col) = hi;
        }
    }
}

// ---------------- propagation: 16 lanes per destination node -----------------
// fp16 z: 16 lanes x uint2 (8B) = exactly one 128B line per gathered row.
__global__ __launch_bounds__(256) void prop_kernel(int iter, float* __restrict__ dout,
                                                   int N, int niter)
{
    int node = (blockIdx.x * blockDim.x + threadIdx.x) >> 4;
    int lane = threadIdx.x & 15;
    if (node >= N) return;

    const __half* zin = (const __half*)((iter & 1) ? g_z1v : g_z0v);
    __half* zout16 = (__half*)((iter & 1) ? g_z0v : g_z1v);

    int start = g_rowptr[node];
    int end   = g_rowptr[node + 1];

    float acc[4] = {};
    for (int e0 = start; e0 < end; e0 += 16) {
        int e = e0 + lane;
        int2 ed = make_int2(0, 0);
        if (e < end) ed = g_edge[e];
        int m = min(16, end - e0);
        #pragma unroll 4
        for (int j = 0; j < m; j++) {
            int   sj = __shfl_sync(0xffffffffu, ed.x, j, 16);
            float wj = __int_as_float(__shfl_sync(0xffffffffu, ed.y, j, 16));
            uint2 v = *(const uint2*)(zin + (size_t)sj * HD + 4 * lane);
            float2 f0 = __half22float2(*(__half2*)&v.x);
            float2 f1 = __half22float2(*(__half2*)&v.y);
            acc[0] += wj * f0.x; acc[1] += wj * f0.y;
            acc[2] += wj * f1.x; acc[3] += wj * f1.y;
        }
    }

    const __half* gh = (const __half*)g_hv;
    uint2 hv = *(const uint2*)(gh + (size_t)node * HD + 4 * lane);
    float2 h0 = __half22float2(*(__half2*)&hv.x);
    float2 h1 = __half22float2(*(__half2*)&hv.y);
    float o0 = (1.0f - ALPHAF) * acc[0] + ALPHAF * h0.x;
    float o1 = (1.0f - ALPHAF) * acc[1] + ALPHAF * h0.y;
    float o2 = (1.0f - ALPHAF) * acc[2] + ALPHAF * h1.x;
    float o3 = (1.0f - ALPHAF) * acc[3] + ALPHAF * h1.y;

    if (iter == niter - 1) {
        *(float4*)(dout + (size_t)node * HD + 4 * lane) = make_float4(o0, o1, o2, o3);
    } else {
        __half2 p0 = __float22half2_rn(make_float2(o0, o1));
        __half2 p1 = __float22half2_rn(make_float2(o2, o3));
        uint2 u;
        u.x = *(unsigned int*)&p0;
        u.y = *(unsigned int*)&p1;
        *(uint2*)(zout16 + (size_t)node * HD + 4 * lane) = u;
    }
}

// ---------------- launcher ----------------------------------------------------
extern "C" void kernel_launch(void* const* d_in, const int* in_sizes, int n_in,
                              void* d_out, int out_size)
{
    const float* x  = (const float*)d_in[0];
    const int*   ei = (const int*)  d_in[1];
    const float* ew = (const float*)d_in[2];
    const float* W0 = (const float*)d_in[3];
    const float* b0 = (const float*)d_in[4];
    const float* W1 = (const float*)d_in[5];
    const float* b1 = (const float*)d_in[6];
    float* out = (float*)d_out;

    int N = in_sizes[0] / FIN;
    int E = in_sizes[2];
    int total = E + N;

    int tpb = 256;
    int nblk = (N + tpb - 1) / tpb;
    int eblk = (total + tpb - 1) / tpb;
    if (eblk > 4096) eblk = 4096;
    int sblk = (N + SCANB - 1) / SCANB;

    zero_kernel<<<nblk, tpb>>>(N);
    degcnt_kernel<<<eblk, tpb>>>(ei, ew, E, N);
    dinv_kernel<<<nblk, tpb>>>(N);
    scan1_kernel<<<sblk, SCANB>>>(N);
    scan2_kernel<<<1, MAXBLK>>>(sblk);
    scan3_kernel<<<sblk, SCANB>>>(N, total);
    scatter_kernel<<<eblk, tpb>>>(ei, ew, E, N);
    mlp_kernel<<<(N + 127) / 128, 256>>>(x, W0, b0, W1, b1, N);

    int pblk = (N * 16 + tpb - 1) / tpb;
    for (int it = 0; it < NITER; it++)
        prop_kernel<<<pblk, tpb>>>(it, out, N, NITER);
}